// round 9
// baseline (speedup 1.0000x reference)
#include <cuda_runtime.h>

// Problem constants
#define B_ 4
#define S_ 256
#define H_ 8
#define D_ 64
#define HID_ 512
#define M_ (B_ * S_)   // 1024 rows for all projections

// Scratch (allocation-free rule: __device__ globals)
__device__ float g_q[M_ * HID_];
__device__ float g_k[M_ * HID_];
__device__ float g_v[M_ * HID_];
__device__ float g_x[M_ * HID_];

// ---------------------------------------------------------------------------
// GEMM: C[M,N] = A[M,K] @ W[K,N] + bias[N]   (fp32, 64x64 tile, BK=16, 4x4/thr)
// ---------------------------------------------------------------------------
__global__ __launch_bounds__(256) void gemm_bias_kernel(
    const float* __restrict__ A, const float* __restrict__ W,
    const float* __restrict__ bias, float* __restrict__ C,
    int M, int N, int K)
{
    __shared__ __align__(16) float As[16][64];
    __shared__ __align__(16) float Bs[16][64];

    const int bn = blockIdx.x * 64;
    const int bm = blockIdx.y * 64;
    const int tid = threadIdx.x;
    const int tx = tid & 15;          // column group (4 cols)
    const int ty = tid >> 4;          // row group (4 rows)

    const int aRow = tid >> 2;            // 0..63
    const int aCol = (tid & 3) * 4;       // 0,4,8,12
    const int bRow = tid >> 4;            // 0..15
    const int bCol = (tid & 15) * 4;      // 0..60

    float acc[4][4] = {};

    for (int kb = 0; kb < K; kb += 16) {
        float4 av = *reinterpret_cast<const float4*>(A + (size_t)(bm + aRow) * K + kb + aCol);
        As[aCol + 0][aRow] = av.x;
        As[aCol + 1][aRow] = av.y;
        As[aCol + 2][aRow] = av.z;
        As[aCol + 3][aRow] = av.w;
        *reinterpret_cast<float4*>(&Bs[bRow][bCol]) =
            *reinterpret_cast<const float4*>(W + (size_t)(kb + bRow) * N + bn + bCol);
        __syncthreads();

        #pragma unroll
        for (int kk = 0; kk < 16; kk++) {
            const float4 a4 = *reinterpret_cast<const float4*>(&As[kk][ty * 4]);
            const float4 b4 = *reinterpret_cast<const float4*>(&Bs[kk][tx * 4]);
            const float a[4] = {a4.x, a4.y, a4.z, a4.w};
            const float b[4] = {b4.x, b4.y, b4.z, b4.w};
            #pragma unroll
            for (int i = 0; i < 4; i++)
                #pragma unroll
                for (int j = 0; j < 4; j++)
                    acc[i][j] = fmaf(a[i], b[j], acc[i][j]);
        }
        __syncthreads();
    }

    const int col = bn + tx * 4;
    const float4 bb = *reinterpret_cast<const float4*>(bias + col);
    #pragma unroll
    for (int i = 0; i < 4; i++) {
        const int row = bm + ty * 4 + i;
        float4 o;
        o.x = acc[i][0] + bb.x;
        o.y = acc[i][1] + bb.y;
        o.z = acc[i][2] + bb.z;
        o.w = acc[i][3] + bb.w;
        *reinterpret_cast<float4*>(C + (size_t)row * N + col) = o;
    }
}

// ---------------------------------------------------------------------------
// Fused GRPE attention: one CTA per (b,h,s) row.
//   score[t] = (q_s·k_t + q_s·spq[s,t] + k_s·spk[s,t]) * D^-0.5 + attn_bias[s,t]
//   softmax over t, then out[d] = sum_t p[t] * v[t,d]
// ---------------------------------------------------------------------------
__global__ __launch_bounds__(256) void attn_grpe_kernel(
    const float* __restrict__ qh, const float* __restrict__ kh,
    const float* __restrict__ vh, const float* __restrict__ abias,
    const float* __restrict__ spq, const float* __restrict__ spk,
    float* __restrict__ xo)
{
    const int s = blockIdx.x;
    const int h = blockIdx.y;
    const int b = blockIdx.z;
    const int tid = threadIdx.x;
    const int lane = tid & 31;
    const int w = tid >> 5;
    const int half = lane >> 4;   // which of 2 t's this half-warp handles
    const int l16 = lane & 15;    // lane within 16 (covers D=64 via float4)

    __shared__ __align__(16) float sh_q[D_];
    __shared__ __align__(16) float sh_k[D_];
    __shared__ float sc[S_];
    __shared__ float sb[S_];
    __shared__ float pvp[4][D_];
    __shared__ float redm[8], reds[8];

    const int bh = b * H_ + h;
    const float* qrow = qh + (size_t)(b * S_ + s) * HID_ + h * D_;
    const float* krow = kh + (size_t)(b * S_ + s) * HID_ + h * D_;
    if (tid < D_)            sh_q[tid]       = qrow[tid];
    else if (tid < 2 * D_)   sh_k[tid - D_]  = krow[tid - D_];
    sb[tid] = abias[((size_t)bh * S_ + s) * S_ + tid];
    __syncthreads();

    const float4 q4 = reinterpret_cast<const float4*>(sh_q)[l16];
    const float4 k4 = reinterpret_cast<const float4*>(sh_k)[l16];

    const size_t rowbase = ((size_t)bh * S_ + s) * (size_t)(S_ * D_);
    const float4* spq4 = reinterpret_cast<const float4*>(spq + rowbase);
    const float4* spk4 = reinterpret_cast<const float4*>(spk + rowbase);

    // Each warp covers t in [w*32, w*32+32), 2 t's per iteration.
    #pragma unroll 4
    for (int i = 0; i < 16; i++) {
        const int t = w * 32 + 2 * i + half;
        const int off = t * (D_ / 4) + l16;          // float4 index
        const float4 aq = spq4[off];
        const float4 ak = spk4[off];
        const float4 kk =
            reinterpret_cast<const float4*>(kh + (size_t)(b * S_ + t) * HID_ + h * D_)[l16];
        float p = q4.x * (kk.x + aq.x) + q4.y * (kk.y + aq.y)
                + q4.z * (kk.z + aq.z) + q4.w * (kk.w + aq.w)
                + k4.x * ak.x + k4.y * ak.y + k4.z * ak.z + k4.w * ak.w;
        // reduce across the 16 lanes of this half-warp
        p += __shfl_xor_sync(0xffffffffu, p, 8);
        p += __shfl_xor_sync(0xffffffffu, p, 4);
        p += __shfl_xor_sync(0xffffffffu, p, 2);
        p += __shfl_xor_sync(0xffffffffu, p, 1);
        if (l16 == 0) sc[t] = p * 0.125f + sb[t];
    }
    __syncthreads();

    // ---- softmax over 256 scores ----
    const float v0 = sc[tid];
    float m = v0;
    #pragma unroll
    for (int o = 16; o > 0; o >>= 1) m = fmaxf(m, __shfl_xor_sync(0xffffffffu, m, o));
    if (lane == 0) redm[w] = m;
    __syncthreads();
    float gm = redm[0];
    #pragma unroll
    for (int j = 1; j < 8; j++) gm = fmaxf(gm, redm[j]);

    const float e = __expf(v0 - gm);
    sc[tid] = e;                                  // own slot only; published at next barrier
    float sum = e;
    #pragma unroll
    for (int o = 16; o > 0; o >>= 1) sum += __shfl_xor_sync(0xffffffffu, sum, o);
    if (lane == 0) reds[w] = sum;
    __syncthreads();
    float tot = reds[0];
    #pragma unroll
    for (int j = 1; j < 8; j++) tot += reds[j];
    const float inv = 1.0f / tot;

    // ---- P @ V : 4 groups of 64 threads, each over 64 t's ----
    const int g = tid >> 6;
    const int d = tid & 63;
    const float* vbase = vh + (size_t)(b * S_ + g * 64) * HID_ + h * D_ + d;
    float acc = 0.0f;
    #pragma unroll 8
    for (int i = 0; i < 64; i++)
        acc = fmaf(sc[g * 64 + i], vbase[(size_t)i * HID_], acc);
    pvp[g][d] = acc;
    __syncthreads();

    if (tid < D_) {
        const float r = (pvp[0][tid] + pvp[1][tid] + pvp[2][tid] + pvp[3][tid]) * inv;
        xo[(size_t)(b * S_ + s) * HID_ + h * D_ + tid] = r;
    }
}

// ---------------------------------------------------------------------------
// Launch
// ---------------------------------------------------------------------------
extern "C" void kernel_launch(void* const* d_in, const int* in_sizes, int n_in,
                              void* d_out, int out_size)
{
    const float* q    = (const float*)d_in[0];
    const float* k    = (const float*)d_in[1];
    const float* v    = (const float*)d_in[2];
    const float* ab   = (const float*)d_in[3];
    const float* spq  = (const float*)d_in[4];
    const float* spk  = (const float*)d_in[5];
    const float* Wq   = (const float*)d_in[6];
    const float* bq   = (const float*)d_in[7];
    const float* Wk   = (const float*)d_in[8];
    const float* bk   = (const float*)d_in[9];
    const float* Wv   = (const float*)d_in[10];
    const float* bv   = (const float*)d_in[11];
    const float* Wo   = (const float*)d_in[12];
    const float* bo   = (const float*)d_in[13];
    float* out        = (float*)d_out;

    void *pq = nullptr, *pk = nullptr, *pv = nullptr, *px = nullptr;
    cudaGetSymbolAddress(&pq, g_q);
    cudaGetSymbolAddress(&pk, g_k);
    cudaGetSymbolAddress(&pv, g_v);
    cudaGetSymbolAddress(&px, g_x);

    const dim3 gg(HID_ / 64, M_ / 64);   // (8, 16) = 128 blocks
    gemm_bias_kernel<<<gg, 256>>>(q, Wq, bq, (float*)pq, M_, HID_, HID_);
    gemm_bias_kernel<<<gg, 256>>>(k, Wk, bk, (float*)pk, M_, HID_, HID_);
    gemm_bias_kernel<<<gg, 256>>>(v, Wv, bv, (float*)pv, M_, HID_, HID_);

    const dim3 ga(S_, H_, B_);           // 8192 blocks
    attn_grpe_kernel<<<ga, 256>>>((const float*)pq, (const float*)pk, (const float*)pv,
                                  ab, spq, spk, (float*)px);

    gemm_bias_kernel<<<gg, 256>>>((const float*)px, Wo, bo, out, M_, HID_, HID_);
}

// round 10
// speedup vs baseline: 1.2412x; 1.2412x over previous
#include <cuda_runtime.h>

// Problem constants
#define B_ 4
#define S_ 256
#define H_ 8
#define D_ 64
#define HID_ 512
#define M_ (B_ * S_)   // 1024 rows for all projections

// Scratch (allocation-free rule: __device__ globals)
__device__ float g_q[M_ * HID_];
__device__ float g_k[M_ * HID_];
__device__ float g_v[M_ * HID_];
__device__ float g_x[M_ * HID_];

// ---------------------------------------------------------------------------
// Packed f32x2 helpers (sm_103a)
// ---------------------------------------------------------------------------
__device__ __forceinline__ unsigned long long pack2(float lo, float hi) {
    unsigned long long r;
    asm("mov.b64 %0, {%1, %2};" : "=l"(r) : "f"(lo), "f"(hi));
    return r;
}
__device__ __forceinline__ float2 unpack2(unsigned long long v) {
    float2 r;
    asm("mov.b64 {%0, %1}, %2;" : "=f"(r.x), "=f"(r.y) : "l"(v));
    return r;
}
__device__ __forceinline__ void ffma2(unsigned long long& d,
                                      unsigned long long a, unsigned long long b) {
    asm("fma.rn.f32x2 %0, %1, %2, %0;" : "+l"(d) : "l"(a), "l"(b));
}
__device__ __forceinline__ unsigned long long add2(unsigned long long a,
                                                   unsigned long long b) {
    unsigned long long r;
    asm("add.rn.f32x2 %0, %1, %2;" : "=l"(r) : "l"(a), "l"(b));
    return r;
}
__device__ __forceinline__ unsigned long long mul2(unsigned long long a,
                                                   unsigned long long b) {
    unsigned long long r;
    asm("mul.rn.f32x2 %0, %1, %2;" : "=l"(r) : "l"(a), "l"(b));
    return r;
}

// ---------------------------------------------------------------------------
// GEMM: C[M,N] = A[M,K] @ W[K,N] + bias[N]  (fp32 via f32x2, 64x64 tile, BK=16)
// Up to 3 independent GEMMs in one launch, selected by blockIdx.z.
// ---------------------------------------------------------------------------
struct GemmArgs {
    const float* A;
    const float* W;
    const float* bias;
    float* C;
};

__global__ __launch_bounds__(256) void gemm_bias3_kernel(
    GemmArgs g0, GemmArgs g1, GemmArgs g2, int M, int N, int K)
{
    const GemmArgs g = (blockIdx.z == 0) ? g0 : ((blockIdx.z == 1) ? g1 : g2);
    const float* __restrict__ A    = g.A;
    const float* __restrict__ W    = g.W;
    const float* __restrict__ bias = g.bias;
    float* __restrict__ C          = g.C;

    __shared__ __align__(16) float As[16][64];
    __shared__ __align__(16) float Bs[16][64];

    const int bn = blockIdx.x * 64;
    const int bm = blockIdx.y * 64;
    const int tid = threadIdx.x;
    const int tx = tid & 15;          // column group (4 cols)
    const int ty = tid >> 4;          // row group (4 rows)

    const int aRow = tid >> 2;            // 0..63
    const int aCol = (tid & 3) * 4;       // 0,4,8,12
    const int bRow = tid >> 4;            // 0..15
    const int bCol = (tid & 15) * 4;      // 0..60

    unsigned long long acc2[4][2] = {};   // packed (0.0f, 0.0f)

    for (int kb = 0; kb < K; kb += 16) {
        float4 av = *reinterpret_cast<const float4*>(A + (size_t)(bm + aRow) * K + kb + aCol);
        As[aCol + 0][aRow] = av.x;
        As[aCol + 1][aRow] = av.y;
        As[aCol + 2][aRow] = av.z;
        As[aCol + 3][aRow] = av.w;
        *reinterpret_cast<float4*>(&Bs[bRow][bCol]) =
            *reinterpret_cast<const float4*>(W + (size_t)(kb + bRow) * N + bn + bCol);
        __syncthreads();

        #pragma unroll
        for (int kk = 0; kk < 16; kk++) {
            const float4 a4 = *reinterpret_cast<const float4*>(&As[kk][ty * 4]);
            const ulonglong2 b2 = *reinterpret_cast<const ulonglong2*>(&Bs[kk][tx * 4]);
            const unsigned long long aa0 = pack2(a4.x, a4.x);
            const unsigned long long aa1 = pack2(a4.y, a4.y);
            const unsigned long long aa2 = pack2(a4.z, a4.z);
            const unsigned long long aa3 = pack2(a4.w, a4.w);
            ffma2(acc2[0][0], aa0, b2.x);  ffma2(acc2[0][1], aa0, b2.y);
            ffma2(acc2[1][0], aa1, b2.x);  ffma2(acc2[1][1], aa1, b2.y);
            ffma2(acc2[2][0], aa2, b2.x);  ffma2(acc2[2][1], aa2, b2.y);
            ffma2(acc2[3][0], aa3, b2.x);  ffma2(acc2[3][1], aa3, b2.y);
        }
        __syncthreads();
    }

    const int col = bn + tx * 4;
    const float4 bb = *reinterpret_cast<const float4*>(bias + col);
    #pragma unroll
    for (int i = 0; i < 4; i++) {
        const int row = bm + ty * 4 + i;
        const float2 c01 = unpack2(acc2[i][0]);
        const float2 c23 = unpack2(acc2[i][1]);
        float4 o;
        o.x = c01.x + bb.x;
        o.y = c01.y + bb.y;
        o.z = c23.x + bb.z;
        o.w = c23.y + bb.w;
        *reinterpret_cast<float4*>(C + (size_t)row * N + col) = o;
    }
}

// ---------------------------------------------------------------------------
// Fused GRPE attention: one CTA per (b,h,s) row.
//   score[t] = (q_s·k_t + q_s·spq[s,t] + k_s·spk[s,t]) * D^-0.5 + attn_bias[s,t]
//   softmax over t, then out[d] = sum_t p[t] * v[t,d]
// ---------------------------------------------------------------------------
__global__ __launch_bounds__(256, 5) void attn_grpe_kernel(
    const float* __restrict__ qh, const float* __restrict__ kh,
    const float* __restrict__ vh, const float* __restrict__ abias,
    const float* __restrict__ spq, const float* __restrict__ spk,
    float* __restrict__ xo)
{
    const int s = blockIdx.x;
    const int h = blockIdx.y;
    const int b = blockIdx.z;
    const int tid = threadIdx.x;
    const int lane = tid & 31;
    const int w = tid >> 5;
    const int half = lane >> 4;   // which of 2 t's this half-warp handles
    const int l16 = lane & 15;    // lane within 16 (covers D=64 via float4)

    __shared__ __align__(16) float sh_q[D_];
    __shared__ __align__(16) float sh_k[D_];
    __shared__ float sc[S_];
    __shared__ float sb[S_];
    __shared__ __align__(16) float pvp[16][D_];
    __shared__ float redm[8], reds[8];

    const int bh = b * H_ + h;
    const float* qrow = qh + (size_t)(b * S_ + s) * HID_ + h * D_;
    const float* krow = kh + (size_t)(b * S_ + s) * HID_ + h * D_;
    if (tid < D_)            sh_q[tid]       = qrow[tid];
    else if (tid < 2 * D_)   sh_k[tid - D_]  = krow[tid - D_];
    sb[tid] = abias[((size_t)bh * S_ + s) * S_ + tid];
    __syncthreads();

    // q/k halves as packed f32x2
    const float4 q4 = reinterpret_cast<const float4*>(sh_q)[l16];
    const float4 k4 = reinterpret_cast<const float4*>(sh_k)[l16];
    const unsigned long long q01 = pack2(q4.x, q4.y);
    const unsigned long long q23 = pack2(q4.z, q4.w);
    const unsigned long long k01 = pack2(k4.x, k4.y);
    const unsigned long long k23 = pack2(k4.z, k4.w);

    const size_t rowbase = ((size_t)bh * S_ + s) * (size_t)(S_ * D_);
    const ulonglong2* spq2 = reinterpret_cast<const ulonglong2*>(spq + rowbase);
    const ulonglong2* spk2 = reinterpret_cast<const ulonglong2*>(spk + rowbase);

    // Each warp covers t in [w*32, w*32+32), 2 t's per iteration.
    #pragma unroll 4
    for (int i = 0; i < 16; i++) {
        const int t = w * 32 + 2 * i + half;
        const int off = t * (D_ / 4) + l16;          // 16B-granule index
        const ulonglong2 aq = spq2[off];
        const ulonglong2 ak = spk2[off];
        const ulonglong2 kk = reinterpret_cast<const ulonglong2*>(
            kh + (size_t)(b * S_ + t) * HID_ + h * D_)[l16];
        unsigned long long p2 = mul2(q01, add2(kk.x, aq.x));
        ffma2(p2, q23, add2(kk.y, aq.y));
        ffma2(p2, k01, ak.x);
        ffma2(p2, k23, ak.y);
        const float2 pf = unpack2(p2);
        float p = pf.x + pf.y;
        // reduce across the 16 lanes of this half-warp
        p += __shfl_xor_sync(0xffffffffu, p, 8);
        p += __shfl_xor_sync(0xffffffffu, p, 4);
        p += __shfl_xor_sync(0xffffffffu, p, 2);
        p += __shfl_xor_sync(0xffffffffu, p, 1);
        if (l16 == 0) sc[t] = p * 0.125f + sb[t];
    }
    __syncthreads();

    // ---- softmax over 256 scores ----
    const float v0 = sc[tid];
    float m = v0;
    #pragma unroll
    for (int o = 16; o > 0; o >>= 1) m = fmaxf(m, __shfl_xor_sync(0xffffffffu, m, o));
    if (lane == 0) redm[w] = m;
    __syncthreads();
    float gm = redm[0];
    #pragma unroll
    for (int j = 1; j < 8; j++) gm = fmaxf(gm, redm[j]);

    const float e = __expf(v0 - gm);
    sc[tid] = e;                                  // own slot only; published at next barrier
    float sum = e;
    #pragma unroll
    for (int o = 16; o > 0; o >>= 1) sum += __shfl_xor_sync(0xffffffffu, sum, o);
    if (lane == 0) reds[w] = sum;
    __syncthreads();
    float tot = reds[0];
    #pragma unroll
    for (int j = 1; j < 8; j++) tot += reds[j];
    const float inv = 1.0f / tot;

    // ---- P @ V : 16 groups of 16 threads; group g covers t in [g*16, g*16+16),
    //      each thread owns a float4 of d. Short latency chains, f32x2 accum.
    const int g  = tid >> 4;      // 0..15
    const int ld = tid & 15;      // float4 index over D
    const float* vbase = vh + (size_t)(b * S_) * HID_ + h * D_;
    unsigned long long acc01 = 0ull, acc23 = 0ull;
    #pragma unroll
    for (int i = 0; i < 16; i++) {
        const int t = g * 16 + i;
        const float wt = sc[t];
        const unsigned long long w2 = pack2(wt, wt);
        const ulonglong2 v2 = reinterpret_cast<const ulonglong2*>(
            vbase + (size_t)t * HID_)[ld];
        ffma2(acc01, w2, v2.x);
        ffma2(acc23, w2, v2.y);
    }
    {
        const float2 a01 = unpack2(acc01);
        const float2 a23 = unpack2(acc23);
        float4 o; o.x = a01.x; o.y = a01.y; o.z = a23.x; o.w = a23.y;
        *reinterpret_cast<float4*>(&pvp[g][ld * 4]) = o;
    }
    __syncthreads();

    // Tree-reduce the 16 partial groups: 4 threads per d sum 4 groups each.
    const int d  = tid & 63;
    const int gq = tid >> 6;      // 0..3
    const float part = pvp[gq * 4 + 0][d] + pvp[gq * 4 + 1][d]
                     + pvp[gq * 4 + 2][d] + pvp[gq * 4 + 3][d];
    __syncthreads();
    pvp[gq][d] = part;
    __syncthreads();

    if (tid < D_) {
        const float r = (pvp[0][tid] + pvp[1][tid] + pvp[2][tid] + pvp[3][tid]) * inv;
        xo[(size_t)(b * S_ + s) * HID_ + h * D_ + tid] = r;
    }
}

// ---------------------------------------------------------------------------
// Launch
// ---------------------------------------------------------------------------
extern "C" void kernel_launch(void* const* d_in, const int* in_sizes, int n_in,
                              void* d_out, int out_size)
{
    const float* q    = (const float*)d_in[0];
    const float* k    = (const float*)d_in[1];
    const float* v    = (const float*)d_in[2];
    const float* ab   = (const float*)d_in[3];
    const float* spq  = (const float*)d_in[4];
    const float* spk  = (const float*)d_in[5];
    const float* Wq   = (const float*)d_in[6];
    const float* bq   = (const float*)d_in[7];
    const float* Wk   = (const float*)d_in[8];
    const float* bk   = (const float*)d_in[9];
    const float* Wv   = (const float*)d_in[10];
    const float* bv   = (const float*)d_in[11];
    const float* Wo   = (const float*)d_in[12];
    const float* bo   = (const float*)d_in[13];
    float* out        = (float*)d_out;

    void *pq = nullptr, *pk = nullptr, *pv = nullptr, *px = nullptr;
    cudaGetSymbolAddress(&pq, g_q);
    cudaGetSymbolAddress(&pk, g_k);
    cudaGetSymbolAddress(&pv, g_v);
    cudaGetSymbolAddress(&px, g_x);

    // Fused Q/K/V projections: one launch, 384 CTAs (z selects the GEMM).
    GemmArgs gq_args = { q, Wq, bq, (float*)pq };
    GemmArgs gk_args = { k, Wk, bk, (float*)pk };
    GemmArgs gv_args = { v, Wv, bv, (float*)pv };
    const dim3 gqkv(HID_ / 64, M_ / 64, 3);
    gemm_bias3_kernel<<<gqkv, 256>>>(gq_args, gk_args, gv_args, M_, HID_, HID_);

    const dim3 ga(S_, H_, B_);           // 8192 blocks
    attn_grpe_kernel<<<ga, 256>>>((const float*)pq, (const float*)pk, (const float*)pv,
                                  ab, spq, spk, (float*)px);

    // Output projection.
    GemmArgs go_args = { (const float*)px, Wo, bo, out };
    const dim3 go(HID_ / 64, M_ / 64, 1);
    gemm_bias3_kernel<<<go, 256>>>(go_args, go_args, go_args, M_, HID_, HID_);
}